// round 3
// baseline (speedup 1.0000x reference)
#include <cuda_runtime.h>
#include <cuda_fp16.h>
#include <cstdint>

#define HW 4096
#define DDIM 64
#define NSLICE 256        // 4096 / 16
#define CS_STRIDE 66

// f pre-packed into mma.sync B-fragment order:
// g_fp[slice s][lane l][16 x b32], b32 (j*2+pair) = halves (k,k+1) of frag j
__device__ uint32_t g_fp[NSLICE * 32 * 16];

// ---------------------------------------------------------------------------
// Kernel 1: build packed B fragments of f[m,d] = cos(8pi*(w0*gx + w1*gy + b))
// ---------------------------------------------------------------------------
__global__ void pos_enc_kernel(const float* __restrict__ w,
                               const float* __restrict__ bias) {
    int idx = blockIdx.x * blockDim.x + threadIdx.x;
    if (idx >= NSLICE * 512) return;
    int s    = idx >> 9;
    int r    = idx & 511;
    int l    = r >> 4;        // lane
    int e    = r & 15;        // b32 slot
    int j    = e >> 1;        // n-frag
    int pair = e & 1;         // k-low / k-high
    int kloc = (l & 3) * 2 + pair * 8;
    int m0   = s * 16 + kloc;
    int d    = j * 8 + (l >> 2);
    float w0 = w[2 * d], w1 = w[2 * d + 1], bd = bias[d];
    float v[2];
#pragma unroll
    for (int t = 0; t < 2; t++) {
        int m = m0 + t;
        int x = m & 63, y = m >> 6;
        float gx = (float)(2 * x - 63) * (1.0f / 64.0f);
        float gy = (float)(2 * y - 63) * (1.0f / 64.0f);
        v[t] = cosf(25.132741228718345f * fmaf(w0, gx, fmaf(w1, gy, bd)));
    }
    __half2 h = __floats2half2_rn(v[0], v[1]);
    g_fp[idx] = *reinterpret_cast<uint32_t*>(&h);
}

// ---------------------------------------------------------------------------
static __device__ __forceinline__ uint32_t e2p(float2 v) {
    __half2 h = __floats2half2_rn(__expf(v.x), __expf(v.y));
    return *reinterpret_cast<uint32_t*>(&h);
}

#define MMA(dst, a0, a1, a2, a3, b0, b1)                                        \
    asm volatile("mma.sync.aligned.m16n8k16.row.col.f32.f16.f16.f32 "           \
                 "{%0,%1,%2,%3},{%4,%5,%6,%7},{%8,%9},{%0,%1,%2,%3};"           \
                 : "+f"(dst[0]), "+f"(dst[1]), "+f"(dst[2]), "+f"(dst[3])       \
                 : "r"(a0), "r"(a1), "r"(a2), "r"(a3), "r"(b0), "r"(b1))

#define LA(dst, s)                                                              \
    do { const float* _p = pA + (size_t)(s) * 16;                               \
        dst[0] = __ldcs((const float2*)_p);                                     \
        dst[1] = __ldcs((const float2*)(_p + 8 * HW));                          \
        dst[2] = __ldcs((const float2*)(_p + 8));                               \
        dst[3] = __ldcs((const float2*)(_p + 8 * HW + 8)); } while (0)

#define LB(dst, s)                                                              \
    do { const uint4* _p = pB + (size_t)(s) * 128;                              \
        dst[0] = __ldg(_p); dst[1] = __ldg(_p + 1);                             \
        dst[2] = __ldg(_p + 2); dst[3] = __ldg(_p + 3); } while (0)

#define STAGE(st, pf, snext)                                                    \
    do {                                                                        \
        uint32_t ra0 = e2p(A[st][0]);                                           \
        uint32_t ra1 = e2p(A[st][1]);                                           \
        uint32_t ra2 = e2p(A[st][2]);                                           \
        uint32_t ra3 = e2p(A[st][3]);                                           \
        if (pf) LA(A[st], snext);                                               \
        const uint32_t* bp = (const uint32_t*)Bv[st];                           \
        MMA(acc[0], ra0, ra1, ra2, ra3, bp[0],  bp[1]);                         \
        MMA(acc[1], ra0, ra1, ra2, ra3, bp[2],  bp[3]);                         \
        MMA(acc[2], ra0, ra1, ra2, ra3, bp[4],  bp[5]);                         \
        MMA(acc[3], ra0, ra1, ra2, ra3, bp[6],  bp[7]);                         \
        MMA(acc[4], ra0, ra1, ra2, ra3, bp[8],  bp[9]);                         \
        MMA(acc[5], ra0, ra1, ra2, ra3, bp[10], bp[11]);                        \
        MMA(acc[6], ra0, ra1, ra2, ra3, bp[12], bp[13]);                        \
        MMA(acc[7], ra0, ra1, ra2, ra3, bp[14], bp[15]);                        \
        MMA(acc[8], ra0, ra1, ra2, ra3, bz, bz);                                \
        if (pf) LB(Bv[st], snext);                                              \
    } while (0)

// ---------------------------------------------------------------------------
// Kernel 2: fused exp + skinny GEMM, no smem/barriers in mainloop.
// CTA = 4 warps x 16 rows = 64 rows of one batch; warp does 16M x 64N, K=4096.
// Z (softmax denom) accumulated by a 9th mma fragment against a ones-column.
// ---------------------------------------------------------------------------
__global__ __launch_bounds__(128)
void gp_kernel(const float* __restrict__ sim, float* __restrict__ out) {
    __shared__ float Cs[64][CS_STRIDE];
    __shared__ float Zs[64];
    __shared__ float Zr[64];

    const int tid = threadIdx.x;
    const int l   = tid & 31;
    const int w   = tid >> 5;
    const int bb  = blockIdx.y;
    const int row0 = blockIdx.x * 64;

    const float* pA = sim + ((size_t)bb * HW + row0 + w * 16 + (l >> 2)) * (size_t)HW
                          + (l & 3) * 2;
    const uint4* pB = ((const uint4*)g_fp) + l * 4;

    float acc[9][4];
#pragma unroll
    for (int i = 0; i < 9; i++)
#pragma unroll
        for (int k = 0; k < 4; k++) acc[i][k] = 0.0f;

    const uint32_t bz = (l < 4) ? 0x3C003C00u : 0u;  // ones in B col 0

    float2 A[2][4];
    uint4  Bv[2][4];
    LA(A[0], 0); LB(Bv[0], 0);
    LA(A[1], 1); LB(Bv[1], 1);

#pragma unroll 1
    for (int s = 0; s < NSLICE; s += 2) {
        const bool pf0 = (s + 2) < NSLICE;
        const bool pf1 = (s + 3) < NSLICE;
        STAGE(0, pf0, s + 2);
        STAGE(1, pf1, s + 3);
    }

    // ---- epilogue: stash C + Z, transpose via smem, divide, coalesced store
    {
        const int lr = w * 16 + (l >> 2);
#pragma unroll
        for (int j = 0; j < 8; j++) {
            const int c0 = j * 8 + (l & 3) * 2;
            *(float2*)&Cs[lr][c0]     = make_float2(acc[j][0], acc[j][1]);
            *(float2*)&Cs[lr + 8][c0] = make_float2(acc[j][2], acc[j][3]);
        }
        if ((l & 3) == 0) {
            Zs[lr]     = acc[8][0];
            Zs[lr + 8] = acc[8][2];
        }
    }
    __syncthreads();
    if (tid < 64) Zr[tid] = 1.0f / Zs[tid];
    __syncthreads();

#pragma unroll
    for (int h = 0; h < 2; h++) {
        const int d = w * 16 + (l >> 2) + h * 8;
        float* go = out + ((size_t)(bb * DDIM + d)) * HW + row0 + (l & 3) * 16;
#pragma unroll
        for (int i = 0; i < 4; i++) {
            const int n = (l & 3) * 16 + i * 4;
            float4 o;
            o.x = Cs[n + 0][d] * Zr[n + 0];
            o.y = Cs[n + 1][d] * Zr[n + 1];
            o.z = Cs[n + 2][d] * Zr[n + 2];
            o.w = Cs[n + 3][d] * Zr[n + 3];
            *(float4*)(go + i * 4) = o;
        }
    }
}

// ---------------------------------------------------------------------------
extern "C" void kernel_launch(void* const* d_in, const int* in_sizes, int n_in,
                              void* d_out, int out_size) {
    const float* sim  = (const float*)d_in[0];  // [4, 4096, 4096] fp32
    const float* w    = (const float*)d_in[1];  // [64, 2] fp32
    const float* bias = (const float*)d_in[2];  // [64] fp32
    float* out = (float*)d_out;                 // [4, 64, 64, 64] fp32

    pos_enc_kernel<<<(NSLICE * 512 + 255) / 256, 256>>>(w, bias);

    dim3 grid(HW / 64, 4);
    gp_kernel<<<grid, 128>>>(sim, out);
}

// round 4
// speedup vs baseline: 1.8553x; 1.8553x over previous
#include <cuda_runtime.h>
#include <cuda_fp16.h>
#include <cstdint>

#define HW 4096
#define DDIM 64
#define NSLICE 256          // total K slices of 16
#define HSLICE 128          // slices per K-half
#define CS_STRIDE 66

// B fragments, lane-major: g_fp[gs][q][lane][4 x b32]; uint4 index = gs*128 + q*32 + lane
// component c of uint4 q: frag j = q*2 + (c>>1), pair = c&1
// K-permutation (matches float4 A loads): frag-pos k for (lane,pair) -> real k = (l&3)*4 + pair*2
__device__ uint32_t g_fp[NSLICE * 4 * 32 * 4];

// ---------------------------------------------------------------------------
// Kernel 1: build packed B fragments of f[m,d] = cos(8pi*(w0*gx + w1*gy + b))
// ---------------------------------------------------------------------------
__global__ void pos_enc_kernel(const float* __restrict__ w,
                               const float* __restrict__ bias) {
    int idx = blockIdx.x * blockDim.x + threadIdx.x;
    if (idx >= NSLICE * 512) return;
    int c    = idx & 3;
    int l    = (idx >> 2) & 31;
    int q    = (idx >> 7) & 3;
    int gs   = idx >> 9;
    int j    = q * 2 + (c >> 1);
    int pair = c & 1;
    int d    = j * 8 + (l >> 2);
    int k    = (l & 3) * 4 + pair * 2;
    int m0   = gs * 16 + k;
    float w0 = w[2 * d], w1 = w[2 * d + 1], bd = bias[d];
    float v[2];
#pragma unroll
    for (int t = 0; t < 2; t++) {
        int m = m0 + t;
        int x = m & 63, y = m >> 6;
        float gx = (float)(2 * x - 63) * (1.0f / 64.0f);
        float gy = (float)(2 * y - 63) * (1.0f / 64.0f);
        v[t] = cosf(25.132741228718345f * fmaf(w0, gx, fmaf(w1, gy, bd)));
    }
    __half2 h = __floats2half2_rn(v[0], v[1]);
    g_fp[idx] = *reinterpret_cast<uint32_t*>(&h);
}

// ---------------------------------------------------------------------------
static __device__ __forceinline__ uint32_t e2p(float a, float b) {
    __half2 h = __floats2half2_rn(__expf(a), __expf(b));
    return *reinterpret_cast<uint32_t*>(&h);
}

#define MMA(dst, a0, a1, a2, a3, b0, b1)                                        \
    asm volatile("mma.sync.aligned.m16n8k16.row.col.f32.f16.f16.f32 "           \
                 "{%0,%1,%2,%3},{%4,%5,%6,%7},{%8,%9},{%0,%1,%2,%3};"           \
                 : "+f"(dst[0]), "+f"(dst[1]), "+f"(dst[2]), "+f"(dst[3])       \
                 : "r"(a0), "r"(a1), "r"(a2), "r"(a3), "r"(b0), "r"(b1))

#define LA(st, s)                                                               \
    do { const float* _p = pA + (size_t)(s) * 16;                               \
        A[st][0] = __ldcs((const float4*)_p);                                   \
        A[st][1] = __ldcs((const float4*)(_p + 8 * HW)); } while (0)

#define LB(st, s)                                                               \
    do { const uint4* _p = pB + (size_t)(s) * 128;                              \
        Bv[st][0] = __ldg(_p);      Bv[st][1] = __ldg(_p + 32);                 \
        Bv[st][2] = __ldg(_p + 64); Bv[st][3] = __ldg(_p + 96); } while (0)

#define STAGE(st, pf, sn)                                                       \
    do {                                                                        \
        uint32_t ra0 = e2p(A[st][0].x, A[st][0].y);                             \
        uint32_t ra2 = e2p(A[st][0].z, A[st][0].w);                             \
        uint32_t ra1 = e2p(A[st][1].x, A[st][1].y);                             \
        uint32_t ra3 = e2p(A[st][1].z, A[st][1].w);                             \
        if (pf) LA(st, sn);                                                     \
        const uint32_t* bp = (const uint32_t*)Bv[st];                           \
        MMA(acc[0], ra0, ra1, ra2, ra3, bp[0],  bp[1]);                         \
        MMA(acc[1], ra0, ra1, ra2, ra3, bp[2],  bp[3]);                         \
        MMA(acc[2], ra0, ra1, ra2, ra3, bp[4],  bp[5]);                         \
        MMA(acc[3], ra0, ra1, ra2, ra3, bp[6],  bp[7]);                         \
        MMA(acc[4], ra0, ra1, ra2, ra3, bp[8],  bp[9]);                         \
        MMA(acc[5], ra0, ra1, ra2, ra3, bp[10], bp[11]);                        \
        MMA(acc[6], ra0, ra1, ra2, ra3, bp[12], bp[13]);                        \
        MMA(acc[7], ra0, ra1, ra2, ra3, bp[14], bp[15]);                        \
        MMA(acc[8], ra0, ra1, ra2, ra3, bz, bz);                                \
        if (pf) LB(st, sn);                                                     \
    } while (0)

// ---------------------------------------------------------------------------
// Kernel 2: 8 warps = 4 row-groups x 2 K-halves. Warp: 16 rows x 64 N x K=2048.
// No smem / barriers in mainloop. Z accumulated by 9th MMA vs ones-column.
// K-halves merged through smem in the epilogue.
// ---------------------------------------------------------------------------
__global__ __launch_bounds__(256, 2)
void gp_kernel(const float* __restrict__ sim, float* __restrict__ out) {
    __shared__ float Cs[64][CS_STRIDE];
    __shared__ float Zs[64];
    __shared__ float Zr[64];

    const int tid = threadIdx.x;
    const int l   = tid & 31;
    const int w   = tid >> 5;
    const int wm  = w & 3;       // row group
    const int kh  = w >> 2;      // K half
    const int bb  = blockIdx.y;
    const int row0 = blockIdx.x * 64;

    const float* pA = sim + ((size_t)bb * HW + row0 + wm * 16 + (l >> 2)) * (size_t)HW
                          + kh * (HSLICE * 16) + (l & 3) * 4;
    const uint4* pB = ((const uint4*)g_fp) + (size_t)kh * HSLICE * 128 + l;

    float acc[9][4];
#pragma unroll
    for (int i = 0; i < 9; i++)
#pragma unroll
        for (int k = 0; k < 4; k++) acc[i][k] = 0.0f;

    const uint32_t bz = (l < 4) ? 0x3C003C00u : 0u;  // ones in B col n=0

    float4 A[2][2];
    uint4  Bv[2][4];
    LA(0, 0); LB(0, 0);
    LA(1, 1); LB(1, 1);

#pragma unroll 1
    for (int s = 0; s < HSLICE; s += 2) {
        const bool pf0 = (s + 2) < HSLICE;
        const bool pf1 = (s + 3) < HSLICE;
        STAGE(0, pf0, s + 2);
        STAGE(1, pf1, s + 3);
    }

    // ---- epilogue: merge K-halves via smem, divide by Z, coalesced store ----
    const int lr = wm * 16 + (l >> 2);
    if (kh == 0) {
#pragma unroll
        for (int j = 0; j < 8; j++) {
            const int c0 = j * 8 + (l & 3) * 2;
            *(float2*)&Cs[lr][c0]     = make_float2(acc[j][0], acc[j][1]);
            *(float2*)&Cs[lr + 8][c0] = make_float2(acc[j][2], acc[j][3]);
        }
        if ((l & 3) == 0) { Zs[lr] = acc[8][0]; Zs[lr + 8] = acc[8][2]; }
    }
    __syncthreads();
    if (kh == 1) {
#pragma unroll
        for (int j = 0; j < 8; j++) {
            const int c0 = j * 8 + (l & 3) * 2;
            Cs[lr][c0]         += acc[j][0];
            Cs[lr][c0 + 1]     += acc[j][1];
            Cs[lr + 8][c0]     += acc[j][2];
            Cs[lr + 8][c0 + 1] += acc[j][3];
        }
        if ((l & 3) == 0) { Zs[lr] += acc[8][0]; Zs[lr + 8] += acc[8][2]; }
    }
    __syncthreads();
    if (tid < 64) Zr[tid] = 1.0f / Zs[tid];
    __syncthreads();

    {
        const int d = tid >> 2, seg = tid & 3;
        float* go = out + ((size_t)(bb * DDIM + d)) * HW + row0 + seg * 16;
#pragma unroll
        for (int i = 0; i < 4; i++) {
            const int n = seg * 16 + i * 4;
            float4 o;
            o.x = Cs[n + 0][d] * Zr[n + 0];
            o.y = Cs[n + 1][d] * Zr[n + 1];
            o.z = Cs[n + 2][d] * Zr[n + 2];
            o.w = Cs[n + 3][d] * Zr[n + 3];
            *(float4*)(go + i * 4) = o;
        }
    }
}

// ---------------------------------------------------------------------------
extern "C" void kernel_launch(void* const* d_in, const int* in_sizes, int n_in,
                              void* d_out, int out_size) {
    const float* sim  = (const float*)d_in[0];  // [4, 4096, 4096] fp32
    const float* w    = (const float*)d_in[1];  // [64, 2] fp32
    const float* bias = (const float*)d_in[2];  // [64] fp32
    float* out = (float*)d_out;                 // [4, 64, 64, 64] fp32

    pos_enc_kernel<<<(NSLICE * 512 + 255) / 256, 256>>>(w, bias);

    dim3 grid(HW / 64, 4);
    gp_kernel<<<grid, 256>>>(sim, out);
}

// round 5
// speedup vs baseline: 2.1830x; 1.1766x over previous
#include <cuda_runtime.h>
#include <cuda_fp16.h>
#include <cstdint>

#define HW 4096
#define DDIM 64
#define NSLICE 256          // total K slices of 16
#define HSLICE 128          // slices per K-half
#define CS_STRIDE 66

// B fragments, lane-major: g_fp[gs][q][lane][4 x b32]; uint4 index = gs*128 + q*32 + lane
// component c of uint4 q: frag j = q*2 + (c>>1), pair = c&1
// K-permutation (matches float4 A loads): real k = (l&3)*4 + pair*2
__device__ uint32_t g_fp[NSLICE * 4 * 32 * 4];

// ---------------------------------------------------------------------------
// Kernel 1: build packed B fragments of f[m,d] = cos(8pi*(w0*gx + w1*gy + b))
// ---------------------------------------------------------------------------
__global__ void pos_enc_kernel(const float* __restrict__ w,
                               const float* __restrict__ bias) {
    int idx = blockIdx.x * blockDim.x + threadIdx.x;
    if (idx >= NSLICE * 512) return;
    int c    = idx & 3;
    int l    = (idx >> 2) & 31;
    int q    = (idx >> 7) & 3;
    int gs   = idx >> 9;
    int j    = q * 2 + (c >> 1);
    int pair = c & 1;
    int d    = j * 8 + (l >> 2);
    int k    = (l & 3) * 4 + pair * 2;
    int m0   = gs * 16 + k;
    float w0 = w[2 * d], w1 = w[2 * d + 1], bd = bias[d];
    float v[2];
#pragma unroll
    for (int t = 0; t < 2; t++) {
        int m = m0 + t;
        int x = m & 63, y = m >> 6;
        float gx = (float)(2 * x - 63) * (1.0f / 64.0f);
        float gy = (float)(2 * y - 63) * (1.0f / 64.0f);
        v[t] = cosf(25.132741228718345f * fmaf(w0, gx, fmaf(w1, gy, bd)));
    }
    __half2 h = __floats2half2_rn(v[0], v[1]);
    g_fp[idx] = *reinterpret_cast<uint32_t*>(&h);
}

// ---------------------------------------------------------------------------
static __device__ __forceinline__ uint32_t e2p(float a, float b) {
    __half2 h = __floats2half2_rn(__expf(a), __expf(b));
    return *reinterpret_cast<uint32_t*>(&h);
}

#define MMA(dst, a0, a1, a2, a3, b0, b1)                                        \
    asm volatile("mma.sync.aligned.m16n8k16.row.col.f32.f16.f16.f32 "           \
                 "{%0,%1,%2,%3},{%4,%5,%6,%7},{%8,%9},{%0,%1,%2,%3};"           \
                 : "+f"(dst[0]), "+f"(dst[1]), "+f"(dst[2]), "+f"(dst[3])       \
                 : "r"(a0), "r"(a1), "r"(a2), "r"(a3), "r"(b0), "r"(b1))

#define LA(st, s)                                                               \
    do { const float* _p = pA + (size_t)(s) * 16;                               \
        A[st][0] = __ldcs((const float4*)_p);                                   \
        A[st][1] = __ldcs((const float4*)(_p + 8 * HW)); } while (0)

// One slice: on-demand B (L1/L2-resident), exp-convert A, deep-prefetch A, 9 MMAs
#define STAGE(st, sidx)                                                         \
    do {                                                                        \
        const uint4* _bp = pB + (size_t)(sidx) * 128;                           \
        uint4 B0 = __ldg(_bp);      uint4 B1 = __ldg(_bp + 32);                 \
        uint4 B2 = __ldg(_bp + 64); uint4 B3 = __ldg(_bp + 96);                 \
        uint32_t ra0 = e2p(A[st][0].x, A[st][0].y);                             \
        uint32_t ra2 = e2p(A[st][0].z, A[st][0].w);                             \
        uint32_t ra1 = e2p(A[st][1].x, A[st][1].y);                             \
        uint32_t ra3 = e2p(A[st][1].z, A[st][1].w);                             \
        if ((sidx) + 4 < HSLICE) LA(st, (sidx) + 4);                            \
        MMA(acc[0], ra0, ra1, ra2, ra3, B0.x, B0.y);                            \
        MMA(acc[1], ra0, ra1, ra2, ra3, B0.z, B0.w);                            \
        MMA(acc[2], ra0, ra1, ra2, ra3, B1.x, B1.y);                            \
        MMA(acc[3], ra0, ra1, ra2, ra3, B1.z, B1.w);                            \
        MMA(acc[4], ra0, ra1, ra2, ra3, B2.x, B2.y);                            \
        MMA(acc[5], ra0, ra1, ra2, ra3, B2.z, B2.w);                            \
        MMA(acc[6], ra0, ra1, ra2, ra3, B3.x, B3.y);                            \
        MMA(acc[7], ra0, ra1, ra2, ra3, B3.z, B3.w);                            \
        MMA(acc[8], ra0, ra1, ra2, ra3, bz, bz);                                \
    } while (0)

// ---------------------------------------------------------------------------
// Kernel 2: 8 warps = 4 row-groups x 2 K-halves. Warp: 16 rows x 64 N x K=2048.
// 4-deep A register pipeline; no smem/barriers in mainloop.
// ---------------------------------------------------------------------------
__global__ __launch_bounds__(256, 2)
void gp_kernel(const float* __restrict__ sim, float* __restrict__ out) {
    __shared__ float Cs[64][CS_STRIDE];
    __shared__ float Zs[64];
    __shared__ float Zr[64];

    const int tid = threadIdx.x;
    const int l   = tid & 31;
    const int w   = tid >> 5;
    const int wm  = w & 3;       // row group
    const int kh  = w >> 2;      // K half
    const int bb  = blockIdx.y;
    const int row0 = blockIdx.x * 64;

    const float* pA = sim + ((size_t)bb * HW + row0 + wm * 16 + (l >> 2)) * (size_t)HW
                          + kh * (HSLICE * 16) + (l & 3) * 4;
    const uint4* pB = ((const uint4*)g_fp) + (size_t)kh * HSLICE * 128 + l;

    float acc[9][4];
#pragma unroll
    for (int i = 0; i < 9; i++)
#pragma unroll
        for (int k = 0; k < 4; k++) acc[i][k] = 0.0f;

    const uint32_t bz = (l < 4) ? 0x3C003C00u : 0u;  // ones in B col n=0

    float4 A[4][2];
    LA(0, 0); LA(1, 1); LA(2, 2); LA(3, 3);

#pragma unroll 1
    for (int s = 0; s < HSLICE; s += 4) {
        STAGE(0, s);
        STAGE(1, s + 1);
        STAGE(2, s + 2);
        STAGE(3, s + 3);
    }

    // ---- epilogue: merge K-halves via smem, divide by Z, coalesced store ----
    const int lr = wm * 16 + (l >> 2);
    if (kh == 0) {
#pragma unroll
        for (int j = 0; j < 8; j++) {
            const int c0 = j * 8 + (l & 3) * 2;
            *(float2*)&Cs[lr][c0]     = make_float2(acc[j][0], acc[j][1]);
            *(float2*)&Cs[lr + 8][c0] = make_float2(acc[j][2], acc[j][3]);
        }
        if ((l & 3) == 0) { Zs[lr] = acc[8][0]; Zs[lr + 8] = acc[8][2]; }
    }
    __syncthreads();
    if (kh == 1) {
#pragma unroll
        for (int j = 0; j < 8; j++) {
            const int c0 = j * 8 + (l & 3) * 2;
            Cs[lr][c0]         += acc[j][0];
            Cs[lr][c0 + 1]     += acc[j][1];
            Cs[lr + 8][c0]     += acc[j][2];
            Cs[lr + 8][c0 + 1] += acc[j][3];
        }
        if ((l & 3) == 0) { Zs[lr] += acc[8][0]; Zs[lr + 8] += acc[8][2]; }
    }
    __syncthreads();
    if (tid < 64) Zr[tid] = 1.0f / Zs[tid];
    __syncthreads();

    {
        const int d = tid >> 2, seg = tid & 3;
        float* go = out + ((size_t)(bb * DDIM + d)) * HW + row0 + seg * 16;
#pragma unroll
        for (int i = 0; i < 4; i++) {
            const int n = seg * 16 + i * 4;
            float4 o;
            o.x = Cs[n + 0][d] * Zr[n + 0];
            o.y = Cs[n + 1][d] * Zr[n + 1];
            o.z = Cs[n + 2][d] * Zr[n + 2];
            o.w = Cs[n + 3][d] * Zr[n + 3];
            *(float4*)(go + i * 4) = o;
        }
    }
}

// ---------------------------------------------------------------------------
extern "C" void kernel_launch(void* const* d_in, const int* in_sizes, int n_in,
                              void* d_out, int out_size) {
    const float* sim  = (const float*)d_in[0];  // [4, 4096, 4096] fp32
    const float* w    = (const float*)d_in[1];  // [64, 2] fp32
    const float* bias = (const float*)d_in[2];  // [64] fp32
    float* out = (float*)d_out;                 // [4, 64, 64, 64] fp32

    pos_enc_kernel<<<(NSLICE * 512 + 255) / 256, 256>>>(w, bias);

    dim3 grid(HW / 64, 4);
    gp_kernel<<<grid, 256>>>(sim, out);
}